// round 1
// baseline (speedup 1.0000x reference)
#include <cuda_runtime.h>
#include <cuda_bf16.h>
#include <math.h>

#define THREADS 256
#define DDIM 256
#define HDIM 256
#define MPATH 8
#define NT 64
#define EPSV 1e-8f

// W packed as bf16x2 pairs, chunk-major for conflict-free LDS.128:
// Wq[((c*256)+h)*4 + j] = bf16x2( W[h][8c+2j], W[h][8c+2j+1] ), c in [0,32), j in [0,4)
__device__ unsigned int Wq_g[32768];

__global__ void prep_kernel(const float* __restrict__ W) {
    int idx = blockIdx.x * blockDim.x + threadIdx.x;   // 0..32767
    int j = idx & 3;
    int h = (idx >> 2) & 255;
    int c = idx >> 10;
    int d = c * 8 + 2 * j;
    float lo = W[h * DDIM + d];
    float hi = W[h * DDIM + d + 1];
    __nv_bfloat162 p = __floats2bfloat162_rn(lo, hi);  // x=lo (low 16 bits)
    Wq_g[idx] = *reinterpret_cast<unsigned int*>(&p);
}

__device__ __forceinline__ unsigned long long ffma2(unsigned long long a,
                                                    unsigned long long b,
                                                    unsigned long long c) {
    unsigned long long d;
    asm("fma.rn.f32x2 %0, %1, %2, %3;" : "=l"(d) : "l"(a), "l"(b), "l"(c));
    return d;
}

__global__ __launch_bounds__(THREADS, 1)
void hete_main_kernel(const int* __restrict__ nodes,
                      const float* __restrict__ homo,
                      const float* __restrict__ bias,
                      const float* __restrict__ out_emb,
                      float* __restrict__ out,
                      int Ntot) {
    extern __shared__ unsigned char smraw[];
    unsigned int* sW = (unsigned int*)smraw;           // 32768 u32 = 128KB
    float* sA   = (float*)(smraw + 131072);            // 2 * 8 * 256 floats = 16KB
    float* sRed = sA + 2 * MPATH * DDIM;               // 8 warps * 24
    float* sTot = sRed + 8 * 24;                       // 20
    float* sAtt = sTot + 20;                           // 8

    const int tid  = threadIdx.x;
    const int base = blockIdx.x * NT;

    // Stage packed W into SMEM (coalesced, conflict-free)
    {
        const uint4* g = (const uint4*)Wq_g;
        uint4* s = (uint4*)sW;
        #pragma unroll
        for (int i = 0; i < 32; i++) s[tid + i * 256] = g[tid + i * 256];
    }
    const float bh = bias[tid];

    // Prefetch node 0's homo rows into registers
    float pre[MPATH];
    if (base < Ntot) {
        #pragma unroll
        for (int m = 0; m < MPATH; m++)
            pre[m] = homo[((size_t)m * Ntot + base) * DDIM + tid];
    }

    for (int it = 0; it < NT; it++) {
        const int n = base + it;
        if (n >= Ntot) break;
        const int buf = it & 1;
        float* sAb = sA + buf * (MPATH * DDIM);

        // Store prefetched homo tile (conflict-free STS)
        #pragma unroll
        for (int m = 0; m < MPATH; m++) sAb[m * DDIM + tid] = pre[m];

        const int tg  = nodes[n];
        const float tgt = out_emb[(size_t)tg * HDIM + tid];

        __syncthreads();

        // Prefetch next node while computing this one
        if (it + 1 < NT && n + 1 < Ntot) {
            #pragma unroll
            for (int m = 0; m < MPATH; m++)
                pre[m] = homo[((size_t)m * Ntot + (n + 1)) * DDIM + tid];
        }

        // GEMV core: z[m] = homo[m,n,:] . W[h,:]   (FFMA2 packed over d-pairs)
        unsigned long long acc[MPATH];
        #pragma unroll
        for (int m = 0; m < MPATH; m++) acc[m] = 0ull;

        const uint4* sW4 = (const uint4*)sW;
        #pragma unroll 4
        for (int c = 0; c < 32; c++) {
            uint4 wq = sW4[c * 256 + tid];
            unsigned long long w2[4];
            {
                unsigned int p;
                p = wq.x; w2[0] = ((unsigned long long)(p & 0xFFFF0000u) << 32) | ((unsigned long long)(p << 16));
                p = wq.y; w2[1] = ((unsigned long long)(p & 0xFFFF0000u) << 32) | ((unsigned long long)(p << 16));
                p = wq.z; w2[2] = ((unsigned long long)(p & 0xFFFF0000u) << 32) | ((unsigned long long)(p << 16));
                p = wq.w; w2[3] = ((unsigned long long)(p & 0xFFFF0000u) << 32) | ((unsigned long long)(p << 16));
            }
            #pragma unroll
            for (int m = 0; m < MPATH; m++) {
                const ulonglong2* ap = (const ulonglong2*)(sAb + m * DDIM + c * 8);
                ulonglong2 v0 = ap[0];  // d = 8c..8c+3 (two f32x2)
                ulonglong2 v1 = ap[1];  // d = 8c+4..8c+7
                acc[m] = ffma2(v0.x, w2[0], acc[m]);
                acc[m] = ffma2(v0.y, w2[1], acc[m]);
                acc[m] = ffma2(v1.x, w2[2], acc[m]);
                acc[m] = ffma2(v1.y, w2[3], acc[m]);
            }
        }

        // Per-thread epilogue: tanh, partial dot/norms
        float v[17];
        #pragma unroll
        for (int m = 0; m < MPATH; m++) {
            float2 az = *(float2*)&acc[m];
            float z = az.x + az.y + bh;
            float hd = tanhf(z);
            v[m]     = hd * tgt;
            v[8 + m] = hd * hd;
        }
        v[16] = tgt * tgt;

        // Warp reduce all 17 values
        #pragma unroll
        for (int i = 0; i < 17; i++) {
            #pragma unroll
            for (int o = 16; o > 0; o >>= 1)
                v[i] += __shfl_xor_sync(0xFFFFFFFFu, v[i], o);
        }
        const int warp = tid >> 5;
        const int lane = tid & 31;
        if (lane == 0) {
            #pragma unroll
            for (int i = 0; i < 17; i++) sRed[warp * 24 + i] = v[i];
        }
        __syncthreads();
        if (tid < 17) {
            float s = 0.f;
            #pragma unroll
            for (int w = 0; w < 8; w++) s += sRed[w * 24 + tid];
            sTot[tid] = s;
        }
        __syncthreads();
        if (tid == 0) {
            float tn = fmaxf(sqrtf(sTot[16]), EPSV);
            float cosv[MPATH];
            float mx = -1e30f;
            #pragma unroll
            for (int m = 0; m < MPATH; m++) {
                float hn = fmaxf(sqrtf(sTot[8 + m]), EPSV);
                float cv = sTot[m] / (hn * tn);
                cosv[m] = cv;
                mx = fmaxf(mx, cv);
            }
            float se = 0.f;
            #pragma unroll
            for (int m = 0; m < MPATH; m++) { cosv[m] = expf(cosv[m] - mx); se += cosv[m]; }
            float inv = 1.f / se;
            #pragma unroll
            for (int m = 0; m < MPATH; m++) sAtt[m] = cosv[m] * inv;
        }
        __syncthreads();

        // Weighted sum over meta-paths (homo tile still resident in SMEM)
        float fo = 0.f;
        #pragma unroll
        for (int m = 0; m < MPATH; m++) fo += sAtt[m] * sAb[m * DDIM + tid];
        out[(size_t)n * DDIM + tid] = fo;
    }
}

extern "C" void kernel_launch(void* const* d_in, const int* in_sizes, int n_in,
                              void* d_out, int out_size) {
    const int*   nodes = (const int*)  d_in[0];
    const float* homo  = (const float*)d_in[1];
    const float* W     = (const float*)d_in[2];
    const float* bias  = (const float*)d_in[3];
    const float* oe    = (const float*)d_in[4];
    float* out = (float*)d_out;
    const int N = in_sizes[0];

    prep_kernel<<<128, 256>>>(W);

    const size_t smem = 131072                      // sW
                      + 2 * MPATH * DDIM * 4        // sA double buffer
                      + 8 * 24 * 4                  // sRed
                      + 20 * 4                      // sTot
                      + 8 * 4;                      // sAtt
    cudaFuncSetAttribute(hete_main_kernel,
                         cudaFuncAttributeMaxDynamicSharedMemorySize, (int)smem);
    const int nb = (N + NT - 1) / NT;
    hete_main_kernel<<<nb, THREADS, smem>>>(nodes, homo, bias, oe, out, N);
}

// round 3
// speedup vs baseline: 6.6901x; 6.6901x over previous
#include <cuda_runtime.h>
#include <cuda_bf16.h>
#include <cstdint>

#define MPATH 8
#define TILE_N 64
#define THREADS 256
#define EPSV 1e-8f

// smem byte offsets from 1024-aligned base
#define OFF_W    0         // 128 KB  W bf16 [256 h][256 d], rowstride 512B, chunk-swizzled
#define OFF_A    131072    // 2 x 32 KB homo bf16 [64 n][256 d]
#define OFF_B    196608    // 1 KB bias fp32
#define OFF_NUM  197632    // 8*64*2 f32
#define OFF_HH   201728    // 8*64*2 f32
#define OFF_TT   205824    // 64*2 f32
#define SMEM_BYTES (206336 + 1024)

__device__ unsigned int Wq_g[32768];   // bf16 W row-major pairs
__device__ float att_g[800008];

__device__ __forceinline__ uint32_t s2u(const void* p){
    uint32_t a;
    asm("{ .reg .u64 t; cvta.to.shared.u64 t, %1; cvt.u32.u64 %0, t; }" : "=r"(a) : "l"(p));
    return a;
}
__device__ __forceinline__ uint32_t pbf2(float a, float b){
    __nv_bfloat162 v = __floats2bfloat162_rn(a, b);
    return *reinterpret_cast<uint32_t*>(&v);
}
__device__ __forceinline__ float tanha(float x){
    float r; asm("tanh.approx.f32 %0, %1;" : "=f"(r) : "f"(x)); return r;
}
#define LDSM4(r0,r1,r2,r3,addr) \
    asm volatile("ldmatrix.sync.aligned.m8n8.x4.shared.b16 {%0,%1,%2,%3}, [%4];" \
        : "=r"(r0), "=r"(r1), "=r"(r2), "=r"(r3) : "r"(addr))
#define MMA16816(c0,c1,c2,c3,a0,a1,a2,a3,b0,b1) \
    asm volatile("mma.sync.aligned.m16n8k16.row.col.f32.bf16.bf16.f32 " \
        "{%0,%1,%2,%3}, {%4,%5,%6,%7}, {%8,%9}, {%0,%1,%2,%3};" \
        : "+f"(c0), "+f"(c1), "+f"(c2), "+f"(c3) \
        : "r"(a0), "r"(a1), "r"(a2), "r"(a3), "r"(b0), "r"(b1))

__global__ void prep_W(const float* __restrict__ W){
    int p = blockIdx.x * blockDim.x + threadIdx.x;   // 0..32767
    int h = p >> 7, d = (p & 127) * 2;
    Wq_g[p] = pbf2(W[h * 256 + d], W[h * 256 + d + 1]);
}

__global__ __launch_bounds__(THREADS, 1)
void hete_mma_kernel(const int* __restrict__ nodes,
                     const float* __restrict__ homo,
                     const float* __restrict__ bias,
                     const float* __restrict__ out_emb,
                     int Ntot){
    extern __shared__ unsigned char smraw[];
    unsigned char* base = (unsigned char*)(((uintptr_t)smraw + 1023) & ~(uintptr_t)1023);

    const int tid  = threadIdx.x;
    const int lane = tid & 31;
    const int wid  = tid >> 5;
    const int mstrip = wid >> 1;      // 0..3  (16-node strip)
    const int nhalf  = wid & 1;       // 0..1  (128-h half)
    const int q      = lane & 3;
    const int n0     = blockIdx.x * TILE_N;
    const int valid  = min(TILE_N, Ntot - n0);

    float* fB   = (float*)(base + OFF_B);
    float* sNum = (float*)(base + OFF_NUM);
    float* sHh  = (float*)(base + OFF_HH);
    float* sTT  = (float*)(base + OFF_TT);
    const uint32_t sWu = s2u(base + OFF_W);
    const uint32_t sAu = s2u(base + OFF_A);

    // ---- stage W into smem with chunk swizzle (row h, 512B stride) ----
    {
        const uint4* g = (const uint4*)Wq_g;   // 8192 16B chunks
        #pragma unroll
        for (int i = 0; i < 32; i++){
            int idx = i * 256 + tid;
            int row = idx >> 5, c = idx & 31;
            *(uint4*)(base + OFF_W + row * 512 + (((c ^ (row & 7)) << 4))) = g[idx];
        }
    }
    fB[tid] = bias[tid];

    // ---- tgt gather into registers (packed bf16), tt = ||tgt||^2 partials ----
    const int r0 = mstrip * 16 + (lane >> 2);
    const int r1 = r0 + 8;
    uint32_t tq0[16], tq1[16];
    float tt0 = 0.f, tt1 = 0.f;
    {
        int gn = n0 + r0;
        if (gn < Ntot){
            const float* tp = out_emb + (size_t)nodes[gn] * 256 + nhalf * 128 + q * 2;
            #pragma unroll
            for (int t = 0; t < 16; t++){
                float2 v = *(const float2*)(tp + t * 8);
                tt0 += v.x * v.x + v.y * v.y;
                tq0[t] = pbf2(v.x, v.y);
            }
        } else {
            #pragma unroll
            for (int t = 0; t < 16; t++) tq0[t] = 0u;
        }
        gn = n0 + r1;
        if (gn < Ntot){
            const float* tp = out_emb + (size_t)nodes[gn] * 256 + nhalf * 128 + q * 2;
            #pragma unroll
            for (int t = 0; t < 16; t++){
                float2 v = *(const float2*)(tp + t * 8);
                tt1 += v.x * v.x + v.y * v.y;
                tq1[t] = pbf2(v.x, v.y);
            }
        } else {
            #pragma unroll
            for (int t = 0; t < 16; t++) tq1[t] = 0u;
        }
    }
    // quad-reduce tt, store per (node, half)
    tt0 += __shfl_xor_sync(0xFFFFFFFFu, tt0, 1); tt0 += __shfl_xor_sync(0xFFFFFFFFu, tt0, 2);
    tt1 += __shfl_xor_sync(0xFFFFFFFFu, tt1, 1); tt1 += __shfl_xor_sync(0xFFFFFFFFu, tt1, 2);
    if (q == 0){ sTT[r0 * 2 + nhalf] = tt0; sTT[r1 * 2 + nhalf] = tt1; }

    // ---- ldmatrix address precompute (XOR-foldable swizzle) ----
    const int arow = mstrip * 16 + (lane & 15);
    const uint32_t PAoff = (uint32_t)(arow * 512) ^
                           ((uint32_t)(((arow & 7) ^ (lane >> 4)) << 4));
    uint32_t PB[8];
    #pragma unroll
    for (int pr = 0; pr < 8; pr++){
        int brow = nhalf * 128 + pr * 16 + ((lane & 16) >> 1) + (lane & 7);
        int hi = (lane >> 3) & 1;
        PB[pr] = (uint32_t)(brow * 512) ^ ((uint32_t)(((brow & 7) ^ hi) << 4));
    }

    // ---- prefetch homo m=0 ----
    float4 pre[16];
    {
        const float4* src = (const float4*)(homo + (size_t)n0 * 256);
        #pragma unroll
        for (int i = 0; i < 16; i++){
            int gi = i * 256 + tid;
            pre[i] = (gi < valid * 64) ? src[gi] : make_float4(0.f,0.f,0.f,0.f);
        }
    }

    float acc[16][4];
    for (int m = 0; m < MPATH; m++){
        // store staged tile (bf16, swizzled)
        unsigned char* bufA = base + OFF_A + (m & 1) * 32768;
        #pragma unroll
        for (int i = 0; i < 16; i++){
            int gi = i * 256 + tid;
            int n = gi >> 6, d4 = gi & 63;
            uint32_t phys = (uint32_t)(n * 512) + ((((d4 >> 1) ^ (n & 7)) << 4)) + (d4 & 1) * 8;
            uint2 o; o.x = pbf2(pre[i].x, pre[i].y); o.y = pbf2(pre[i].z, pre[i].w);
            *(uint2*)(bufA + phys) = o;
        }
        __syncthreads();

        // prefetch next meta-path (overlaps with MMA below)
        if (m + 1 < MPATH){
            const float4* src = (const float4*)(homo + ((size_t)(m + 1) * Ntot + n0) * 256);
            #pragma unroll
            for (int i = 0; i < 16; i++){
                int gi = i * 256 + tid;
                pre[i] = (gi < valid * 64) ? src[gi] : make_float4(0.f,0.f,0.f,0.f);
            }
        }

        #pragma unroll
        for (int t = 0; t < 16; t++){
            acc[t][0] = 0.f; acc[t][1] = 0.f; acc[t][2] = 0.f; acc[t][3] = 0.f;
        }
        const uint32_t bufu = sAu + (m & 1) * 32768;
        #pragma unroll 4
        for (int kk = 0; kk < 16; kk++){
            uint32_t a0, a1, a2, a3;
            LDSM4(a0, a1, a2, a3, bufu + (PAoff ^ (kk << 5)));
            #pragma unroll
            for (int pr = 0; pr < 8; pr++){
                uint32_t b0, b1, b2, b3;
                LDSM4(b0, b1, b2, b3, sWu + (PB[pr] ^ (kk << 5)));
                MMA16816(acc[2*pr][0],   acc[2*pr][1],   acc[2*pr][2],   acc[2*pr][3],
                         a0, a1, a2, a3, b0, b1);
                MMA16816(acc[2*pr+1][0], acc[2*pr+1][1], acc[2*pr+1][2], acc[2*pr+1][3],
                         a0, a1, a2, a3, b2, b3);
            }
        }

        // ---- epilogue: bias + tanh + num/hh partials ----
        float nm0 = 0.f, nm1 = 0.f, hv0 = 0.f, hv1 = 0.f;
        #pragma unroll
        for (int t = 0; t < 16; t++){
            int col = nhalf * 128 + t * 8 + q * 2;
            float2 bb = *(const float2*)(fB + col);
            float ta = tanha(acc[t][0] + bb.x);
            float tb = tanha(acc[t][1] + bb.y);
            float tc = tanha(acc[t][2] + bb.x);
            float td = tanha(acc[t][3] + bb.y);
            float2 g0 = __bfloat1622float2(*reinterpret_cast<__nv_bfloat162*>(&tq0[t]));
            float2 g1 = __bfloat1622float2(*reinterpret_cast<__nv_bfloat162*>(&tq1[t]));
            nm0 += ta * g0.x + tb * g0.y;  hv0 += ta * ta + tb * tb;
            nm1 += tc * g1.x + td * g1.y;  hv1 += tc * tc + td * td;
        }
        nm0 += __shfl_xor_sync(0xFFFFFFFFu, nm0, 1); nm0 += __shfl_xor_sync(0xFFFFFFFFu, nm0, 2);
        nm1 += __shfl_xor_sync(0xFFFFFFFFu, nm1, 1); nm1 += __shfl_xor_sync(0xFFFFFFFFu, nm1, 2);
        hv0 += __shfl_xor_sync(0xFFFFFFFFu, hv0, 1); hv0 += __shfl_xor_sync(0xFFFFFFFFu, hv0, 2);
        hv1 += __shfl_xor_sync(0xFFFFFFFFu, hv1, 1); hv1 += __shfl_xor_sync(0xFFFFFFFFu, hv1, 2);
        if (q == 0){
            sNum[(m * 64 + r0) * 2 + nhalf] = nm0;
            sNum[(m * 64 + r1) * 2 + nhalf] = nm1;
            sHh [(m * 64 + r0) * 2 + nhalf] = hv0;
            sHh [(m * 64 + r1) * 2 + nhalf] = hv1;
        }
    }

    __syncthreads();
    // ---- softmax over meta-paths, one thread per node ----
    if (tid < TILE_N && n0 + tid < Ntot){
        const int node = tid;
        float tn = fmaxf(sqrtf(sTT[node * 2] + sTT[node * 2 + 1]), EPSV);
        float cv[MPATH], mx = -1e30f;
        #pragma unroll
        for (int m = 0; m < MPATH; m++){
            float num = sNum[(m * 64 + node) * 2] + sNum[(m * 64 + node) * 2 + 1];
            float hh  = sHh [(m * 64 + node) * 2] + sHh [(m * 64 + node) * 2 + 1];
            float hn = fmaxf(sqrtf(hh), EPSV);
            cv[m] = num / (hn * tn);
            mx = fmaxf(mx, cv[m]);
        }
        float se = 0.f;
        #pragma unroll
        for (int m = 0; m < MPATH; m++){ cv[m] = __expf(cv[m] - mx); se += cv[m]; }
        float inv = 1.f / se;
        #pragma unroll
        for (int m = 0; m < MPATH; m++) att_g[(size_t)(n0 + node) * 8 + m] = cv[m] * inv;
    }
}

// ---------------- weighted sum (fp32 homo) ----------------
__global__ __launch_bounds__(256)
void finalize_kernel(const float* __restrict__ homo, float* __restrict__ out, int Ntot){
    const int tid = threadIdx.x;
    const int nl = tid >> 6, d4 = tid & 63;
    const int n = blockIdx.x * 4 + nl;
    if (n >= Ntot) return;
    const float4* ap = (const float4*)(att_g + (size_t)n * 8);
    float4 a0 = ap[0], a1 = ap[1];
    float att[8] = {a0.x, a0.y, a0.z, a0.w, a1.x, a1.y, a1.z, a1.w};
    float4 acc = make_float4(0.f, 0.f, 0.f, 0.f);
    #pragma unroll
    for (int m = 0; m < MPATH; m++){
        float4 v = *(const float4*)(homo + ((size_t)m * Ntot + n) * 256 + d4 * 4);
        acc.x += att[m] * v.x; acc.y += att[m] * v.y;
        acc.z += att[m] * v.z; acc.w += att[m] * v.w;
    }
    *(float4*)(out + (size_t)n * 256 + d4 * 4) = acc;
}

extern "C" void kernel_launch(void* const* d_in, const int* in_sizes, int n_in,
                              void* d_out, int out_size){
    const int*   nodes = (const int*)  d_in[0];
    const float* homo  = (const float*)d_in[1];
    const float* W     = (const float*)d_in[2];
    const float* bias  = (const float*)d_in[3];
    const float* oe    = (const float*)d_in[4];
    float* out = (float*)d_out;
    const int N = in_sizes[0];

    prep_W<<<128, 256>>>(W);

    cudaFuncSetAttribute(hete_mma_kernel,
                         cudaFuncAttributeMaxDynamicSharedMemorySize, SMEM_BYTES);
    const int nb = (N + TILE_N - 1) / TILE_N;
    hete_mma_kernel<<<nb, THREADS, SMEM_BYTES>>>(nodes, homo, bias, oe, N);

    finalize_kernel<<<(N + 3) / 4, 256>>>(homo, out, N);
}